// round 2
// baseline (speedup 1.0000x reference)
#include <cuda_runtime.h>
#include <cuda_bf16.h>

// Problem constants
constexpr int Nn = 4096;   // nodes
constexpr int Dd = 256;    // model dim
constexpr int Hh = 8;      // heads
constexpr int HDim = 32;   // head dim
constexpr int Ee = 65536;  // edges

// ---------------------------------------------------------------------------
// Scratch (device globals; no dynamic allocation allowed)
// ---------------------------------------------------------------------------
__device__ float    g_Q[Nn * Dd];
__device__ float    g_K[Nn * Dd];
__device__ float    g_V[Nn * Dd];
__device__ float    g_numer[Nn * Dd];    // sum over edges of (exp(s)-1)*V[col]
__device__ float    g_attn[Nn * Dd];     // softmax-attention output (pre Wo)
__device__ float    g_denom[Nn * Hh];    // sum over edges of (exp(s)-1)
__device__ float    g_vsum[Dd];          // column sums of V
__device__ unsigned g_bitmap[(size_t)Nn * Nn / 32];  // dedup bitmap (2 MB)

// ---------------------------------------------------------------------------
// Zero scratch that is accumulated into each launch
// ---------------------------------------------------------------------------
__global__ void zero_kernel() {
    int idx = blockIdx.x * blockDim.x + threadIdx.x;
    int stride = gridDim.x * blockDim.x;
    for (int i = idx; i < Nn * Dd; i += stride) g_numer[i] = 0.0f;
    for (int i = idx; i < Nn * Hh; i += stride) g_denom[i] = 0.0f;
    for (int i = idx; i < Dd; i += stride) g_vsum[i] = 0.0f;
    for (int i = idx; i < Nn * Nn / 32; i += stride) g_bitmap[i] = 0u;
}

// ---------------------------------------------------------------------------
// Tiled fp32 GEMM:  C[M, 256] = A[M, 256] @ W[256, 256]^T  (+ optional bias)
// Both A and W are row-major with K (=256) contiguous.
// Tile: BM=64, BN=64, BK=32; 256 threads; 4x4 micro-tile per thread.
// ---------------------------------------------------------------------------
__device__ __forceinline__ void gemm_body(const float* __restrict__ A,
                                          const float* __restrict__ W,
                                          const float* __restrict__ bias,
                                          float* __restrict__ C) {
    __shared__ float As[32][68];  // [k][m], padded
    __shared__ float Ws[32][68];  // [k][n]

    const int tid = threadIdx.x;
    const int tx = tid & 15;          // 0..15 -> n
    const int ty = tid >> 4;          // 0..15 -> m
    const int m0 = blockIdx.y * 64;
    const int n0 = blockIdx.x * 64;

    const int lrow = tid >> 3;        // 0..31
    const int lk   = (tid & 7) * 4;   // 0,4,...,28

    float acc[4][4];
#pragma unroll
    for (int i = 0; i < 4; i++)
#pragma unroll
        for (int j = 0; j < 4; j++) acc[i][j] = 0.0f;

    for (int k0 = 0; k0 < Dd; k0 += 32) {
        // Load A tile (64 x 32) transposed into As[k][m]
#pragma unroll
        for (int r = 0; r < 2; r++) {
            int m = lrow + 32 * r;
            float4 a = *(const float4*)&A[(size_t)(m0 + m) * Dd + k0 + lk];
            As[lk + 0][m] = a.x;
            As[lk + 1][m] = a.y;
            As[lk + 2][m] = a.z;
            As[lk + 3][m] = a.w;
        }
        // Load W tile (64 x 32) transposed into Ws[k][n]
#pragma unroll
        for (int r = 0; r < 2; r++) {
            int n = lrow + 32 * r;
            float4 b = *(const float4*)&W[(size_t)(n0 + n) * Dd + k0 + lk];
            Ws[lk + 0][n] = b.x;
            Ws[lk + 1][n] = b.y;
            Ws[lk + 2][n] = b.z;
            Ws[lk + 3][n] = b.w;
        }
        __syncthreads();

#pragma unroll
        for (int kk = 0; kk < 32; kk++) {
            float4 a4 = *(const float4*)&As[kk][ty * 4];
            float4 b4 = *(const float4*)&Ws[kk][tx * 4];
            float a[4] = {a4.x, a4.y, a4.z, a4.w};
            float b[4] = {b4.x, b4.y, b4.z, b4.w};
#pragma unroll
            for (int i = 0; i < 4; i++)
#pragma unroll
                for (int j = 0; j < 4; j++) acc[i][j] += a[i] * b[j];
        }
        __syncthreads();
    }

#pragma unroll
    for (int i = 0; i < 4; i++) {
        int m = m0 + ty * 4 + i;
#pragma unroll
        for (int j = 0; j < 4; j++) {
            int n = n0 + tx * 4 + j;
            float v = acc[i][j];
            if (bias) v += bias[n];
            C[(size_t)m * Dd + n] = v;
        }
    }
}

// QKV: grid.z in {0,1,2} selects which projection
__global__ __launch_bounds__(256) void gemm_qkv_kernel(const float* __restrict__ x,
                                                       const float* __restrict__ Wq,
                                                       const float* __restrict__ Wk,
                                                       const float* __restrict__ Wv) {
    const float* W = (blockIdx.z == 0) ? Wq : (blockIdx.z == 1) ? Wk : Wv;
    float* C = (blockIdx.z == 0) ? g_Q : (blockIdx.z == 1) ? g_K : g_V;
    gemm_body(x, W, nullptr, C);
}

// Output projection: out = attn @ Wo^T + bo
__global__ __launch_bounds__(256) void gemm_out_kernel(const float* __restrict__ Wo,
                                                       const float* __restrict__ bo,
                                                       float* __restrict__ out) {
    gemm_body(g_attn, Wo, bo, out);
}

// ---------------------------------------------------------------------------
// Column sums of V: g_vsum[c] = sum_r V[r][c]
// ---------------------------------------------------------------------------
__global__ void vsum_kernel() {
    int c = threadIdx.x;
    int r0 = blockIdx.x * 64;
    float s = 0.0f;
#pragma unroll 8
    for (int r = 0; r < 64; r++) s += g_V[(size_t)(r0 + r) * Dd + c];
    atomicAdd(&g_vsum[c], s);
}

// ---------------------------------------------------------------------------
// Edge kernel: one warp per edge.
// Lane l covers dims [l*8, l*8+8) = head (l>>2), quarter (l&3).
// edge_index arrives as INT32 (JAX default config downcasts int64 -> int32).
// Indices are defensively masked to [0, Nn) — Nn is a power of two — so a
// dtype surprise shows up as rel_err, not an illegal access.
// ---------------------------------------------------------------------------
__global__ __launch_bounds__(256) void edge_kernel(const int* __restrict__ ei) {
    int warp = (blockIdx.x * blockDim.x + threadIdx.x) >> 5;
    int lane = threadIdx.x & 31;
    if (warp >= Ee) return;

    int row = ei[warp] & (Nn - 1);        // destination node i
    int col = ei[Ee + warp] & (Nn - 1);   // source node j

    // Deduplicate (row,col): set semantics — duplicates have identical scores
    unsigned key = (unsigned)row * (unsigned)Nn + (unsigned)col;
    int skip = 0;
    if (lane == 0) {
        unsigned old = atomicOr(&g_bitmap[key >> 5], 1u << (key & 31));
        skip = (old >> (key & 31)) & 1;
    }
    skip = __shfl_sync(0xffffffffu, skip, 0);
    if (skip) return;

    const float* q = g_Q + (size_t)row * Dd + lane * 8;
    const float* k = g_K + (size_t)col * Dd + lane * 8;
    float4 q1 = *(const float4*)q;
    float4 q2 = *(const float4*)(q + 4);
    float4 k1 = *(const float4*)k;
    float4 k2 = *(const float4*)(k + 4);

    float s = q1.x * k1.x + q1.y * k1.y + q1.z * k1.z + q1.w * k1.w
            + q2.x * k2.x + q2.y * k2.y + q2.z * k2.z + q2.w * k2.w;
    // reduce within each 4-lane head group
    s += __shfl_xor_sync(0xffffffffu, s, 1);
    s += __shfl_xor_sync(0xffffffffu, s, 2);

    const float inv_scale = 0.17677669529663687f;  // 1/sqrt(32)
    float w = expf(s * inv_scale) - 1.0f;

    int h = lane >> 2;
    if ((lane & 3) == 0) atomicAdd(&g_denom[row * Hh + h], w);

    const float* v = g_V + (size_t)col * Dd + lane * 8;
    float* np = g_numer + (size_t)row * Dd + lane * 8;
    float4 v1 = *(const float4*)v;
    float4 v2 = *(const float4*)(v + 4);
    asm volatile("red.global.add.v4.f32 [%0], {%1, %2, %3, %4};"
                 :: "l"(np), "f"(w * v1.x), "f"(w * v1.y), "f"(w * v1.z), "f"(w * v1.w)
                 : "memory");
    asm volatile("red.global.add.v4.f32 [%0], {%1, %2, %3, %4};"
                 :: "l"(np + 4), "f"(w * v2.x), "f"(w * v2.y), "f"(w * v2.z), "f"(w * v2.w)
                 : "memory");
}

// ---------------------------------------------------------------------------
// Combine: attn[i, c] = (vsum[c] + numer[i, c]) / (N + denom[i, c/32])
// ---------------------------------------------------------------------------
__global__ void combine_kernel() {
    int i = blockIdx.x;
    int c = threadIdx.x;
    size_t idx = (size_t)i * Dd + c;
    float d = (float)Nn + g_denom[i * Hh + (c >> 5)];
    g_attn[idx] = (g_vsum[c] + g_numer[idx]) / d;
}

// ---------------------------------------------------------------------------
extern "C" void kernel_launch(void* const* d_in, const int* in_sizes, int n_in,
                              void* d_out, int out_size) {
    const float* x  = (const float*)d_in[0];
    const int*   ei = (const int*)d_in[1];     // int32 (JAX x64 disabled)
    const float* Wq = (const float*)d_in[2];
    const float* Wk = (const float*)d_in[3];
    const float* Wv = (const float*)d_in[4];
    const float* Wo = (const float*)d_in[5];
    const float* bo = (const float*)d_in[6];
    float*       out = (float*)d_out;

    // 1) clear accumulators + dedup bitmap
    zero_kernel<<<1024, 256>>>();

    // 2) Q, K, V projections (z selects the weight)
    gemm_qkv_kernel<<<dim3(Dd / 64, Nn / 64, 3), 256>>>(x, Wq, Wk, Wv);

    // 3) global V column sums
    vsum_kernel<<<Nn / 64, 256>>>();

    // 4) per-edge scores + scatter of (exp(s)-1)*V and (exp(s)-1)
    edge_kernel<<<Ee / 8, 256>>>(ei);

    // 5) softmax combine
    combine_kernel<<<Nn, Dd>>>();

    // 6) output projection with bias
    gemm_out_kernel<<<dim3(Dd / 64, Nn / 64, 1), 256>>>(Wo, bo, out);
}

// round 3
// speedup vs baseline: 1.2631x; 1.2631x over previous
#include <cuda_runtime.h>
#include <cuda_bf16.h>

// Problem constants
constexpr int Nn = 4096;   // nodes
constexpr int Dd = 256;    // model dim
constexpr int Hh = 8;      // heads
constexpr int Ee = 65536;  // edges

// ---------------------------------------------------------------------------
// Scratch (device globals; no dynamic allocation allowed)
// ---------------------------------------------------------------------------
__device__ float    g_Q[Nn * Dd];
__device__ float    g_K[Nn * Dd];
__device__ float    g_V[Nn * Dd];
__device__ float    g_numer[Nn * Dd];    // sum over edges of (exp(s)-1)*V[col]
__device__ float    g_attn[Nn * Dd];     // softmax-attention output (pre Wo)
__device__ float    g_denom[Nn * Hh];    // sum over edges of (exp(s)-1)
__device__ float    g_vsum[Dd];          // column sums of V
__device__ unsigned g_bitmap[(size_t)Nn * Nn / 32];  // dedup bitmap (2 MB)

// ---------------------------------------------------------------------------
// Zero scratch (vectorized 16B stores)
// ---------------------------------------------------------------------------
__global__ void zero_kernel() {
    int idx = blockIdx.x * blockDim.x + threadIdx.x;
    int stride = gridDim.x * blockDim.x;
    float4 fz = make_float4(0.f, 0.f, 0.f, 0.f);
    uint4  uz = make_uint4(0u, 0u, 0u, 0u);
    float4* n4 = (float4*)g_numer;
    uint4*  b4 = (uint4*)g_bitmap;
    for (int i = idx; i < Nn * Dd / 4; i += stride) n4[i] = fz;
    for (int i = idx; i < Nn * Nn / 32 / 4; i += stride) b4[i] = uz;
    for (int i = idx; i < Nn * Hh; i += stride) g_denom[i] = 0.0f;
    for (int i = idx; i < Dd; i += stride) g_vsum[i] = 0.0f;
}

// ---------------------------------------------------------------------------
// fp32 GEMM: C[M,256] = A[M,256] @ W[256,256]^T (+ optional bias)
// BM=64, BN=128, BK=16, 128 threads, 8x8 micro-tile.
// Balanced at the SM level: 16 smem floats per 64 FMAs = 0.25 floats/FMA,
// exactly matching the 32 floats/cyc LDS vs 128 FMA/cyc budget.
// ---------------------------------------------------------------------------
__device__ __forceinline__ void gemm_body(const float* __restrict__ A,
                                          const float* __restrict__ W,
                                          const float* __restrict__ bias,
                                          float* __restrict__ C) {
    __shared__ float As[16][68];    // [k][m]  (BK x BM, padded)
    __shared__ float Ws[16][132];   // [k][n]  (BK x BN, padded)

    const int tid = threadIdx.x;
    const int tx = tid & 15;        // 0..15 -> n groups
    const int ty = tid >> 4;        // 0..7  -> m groups
    const int m0 = blockIdx.y * 64;
    const int n0 = blockIdx.x * 128;

    // Global-load assignments
    const int lr = tid >> 2;        // 0..31 (row within tile)
    const int lk = (tid & 3) * 4;   // 0,4,8,12 (k offset)

    float acc[8][8];
#pragma unroll
    for (int i = 0; i < 8; i++)
#pragma unroll
        for (int j = 0; j < 8; j++) acc[i][j] = 0.0f;

    // Prefetch first K-tile into registers
    float4 pa[2], pw[4];
#pragma unroll
    for (int r = 0; r < 2; r++)
        pa[r] = *(const float4*)&A[(size_t)(m0 + lr + 32 * r) * Dd + lk];
#pragma unroll
    for (int j = 0; j < 4; j++)
        pw[j] = *(const float4*)&W[(size_t)(n0 + lr + 32 * j) * Dd + lk];

    for (int k0 = 0; k0 < Dd; k0 += 16) {
        // Commit prefetched tile to smem (transposed)
#pragma unroll
        for (int r = 0; r < 2; r++) {
            As[lk + 0][lr + 32 * r] = pa[r].x;
            As[lk + 1][lr + 32 * r] = pa[r].y;
            As[lk + 2][lr + 32 * r] = pa[r].z;
            As[lk + 3][lr + 32 * r] = pa[r].w;
        }
#pragma unroll
        for (int j = 0; j < 4; j++) {
            Ws[lk + 0][lr + 32 * j] = pw[j].x;
            Ws[lk + 1][lr + 32 * j] = pw[j].y;
            Ws[lk + 2][lr + 32 * j] = pw[j].z;
            Ws[lk + 3][lr + 32 * j] = pw[j].w;
        }
        __syncthreads();

        // Prefetch next K-tile (overlaps with FMA work below)
        if (k0 + 16 < Dd) {
            int kn = k0 + 16 + lk;
#pragma unroll
            for (int r = 0; r < 2; r++)
                pa[r] = *(const float4*)&A[(size_t)(m0 + lr + 32 * r) * Dd + kn];
#pragma unroll
            for (int j = 0; j < 4; j++)
                pw[j] = *(const float4*)&W[(size_t)(n0 + lr + 32 * j) * Dd + kn];
        }

#pragma unroll
        for (int kk = 0; kk < 16; kk++) {
            float4 a0 = *(const float4*)&As[kk][ty * 4];
            float4 a1 = *(const float4*)&As[kk][32 + ty * 4];
            float4 b0 = *(const float4*)&Ws[kk][tx * 4];
            float4 b1 = *(const float4*)&Ws[kk][64 + tx * 4];
            float a[8] = {a0.x, a0.y, a0.z, a0.w, a1.x, a1.y, a1.z, a1.w};
            float b[8] = {b0.x, b0.y, b0.z, b0.w, b1.x, b1.y, b1.z, b1.w};
#pragma unroll
            for (int i = 0; i < 8; i++)
#pragma unroll
                for (int j = 0; j < 8; j++) acc[i][j] += a[i] * b[j];
        }
        __syncthreads();
    }

    // Epilogue: 2 st.128 per row, 8 rows
#pragma unroll
    for (int i = 0; i < 8; i++) {
        int m = m0 + (i < 4 ? ty * 4 + i : 32 + ty * 4 + (i - 4));
#pragma unroll
        for (int jh = 0; jh < 2; jh++) {
            int n = n0 + jh * 64 + tx * 4;
            float4 v = make_float4(acc[i][jh * 4 + 0], acc[i][jh * 4 + 1],
                                   acc[i][jh * 4 + 2], acc[i][jh * 4 + 3]);
            if (bias) {
                v.x += bias[n + 0]; v.y += bias[n + 1];
                v.z += bias[n + 2]; v.w += bias[n + 3];
            }
            *(float4*)&C[(size_t)m * Dd + n] = v;
        }
    }
}

__global__ __launch_bounds__(128) void gemm_qkv_kernel(const float* __restrict__ x,
                                                       const float* __restrict__ Wq,
                                                       const float* __restrict__ Wk,
                                                       const float* __restrict__ Wv) {
    const float* W = (blockIdx.z == 0) ? Wq : (blockIdx.z == 1) ? Wk : Wv;
    float* C = (blockIdx.z == 0) ? g_Q : (blockIdx.z == 1) ? g_K : g_V;
    gemm_body(x, W, nullptr, C);
}

__global__ __launch_bounds__(128) void gemm_out_kernel(const float* __restrict__ Wo,
                                                       const float* __restrict__ bo,
                                                       float* __restrict__ out) {
    gemm_body(g_attn, Wo, bo, out);
}

// ---------------------------------------------------------------------------
// Column sums of V
// ---------------------------------------------------------------------------
__global__ void vsum_kernel() {
    int c = threadIdx.x;
    int r0 = blockIdx.x * 64;
    float s = 0.0f;
#pragma unroll 8
    for (int r = 0; r < 64; r++) s += g_V[(size_t)(r0 + r) * Dd + c];
    atomicAdd(&g_vsum[c], s);
}

// ---------------------------------------------------------------------------
// Edge kernel: one warp per edge. Lane l covers dims [l*8, l*8+8).
// edge_index is int32; indices defensively masked to [0, Nn).
// ---------------------------------------------------------------------------
__global__ __launch_bounds__(256) void edge_kernel(const int* __restrict__ ei) {
    int warp = (blockIdx.x * blockDim.x + threadIdx.x) >> 5;
    int lane = threadIdx.x & 31;
    if (warp >= Ee) return;

    int row = ei[warp] & (Nn - 1);        // destination node i
    int col = ei[Ee + warp] & (Nn - 1);   // source node j

    // Deduplicate (row,col): set semantics (duplicates have identical scores)
    unsigned key = (unsigned)row * (unsigned)Nn + (unsigned)col;
    int skip = 0;
    if (lane == 0) {
        unsigned old = atomicOr(&g_bitmap[key >> 5], 1u << (key & 31));
        skip = (old >> (key & 31)) & 1;
    }
    skip = __shfl_sync(0xffffffffu, skip, 0);
    if (skip) return;

    const float* q = g_Q + (size_t)row * Dd + lane * 8;
    const float* k = g_K + (size_t)col * Dd + lane * 8;
    const float* v = g_V + (size_t)col * Dd + lane * 8;
    float4 q1 = *(const float4*)q;
    float4 q2 = *(const float4*)(q + 4);
    float4 k1 = *(const float4*)k;
    float4 k2 = *(const float4*)(k + 4);
    float4 v1 = *(const float4*)v;      // independent of score: issue early
    float4 v2 = *(const float4*)(v + 4);

    float s = q1.x * k1.x + q1.y * k1.y + q1.z * k1.z + q1.w * k1.w
            + q2.x * k2.x + q2.y * k2.y + q2.z * k2.z + q2.w * k2.w;
    s += __shfl_xor_sync(0xffffffffu, s, 1);
    s += __shfl_xor_sync(0xffffffffu, s, 2);

    const float inv_scale = 0.17677669529663687f;  // 1/sqrt(32)
    float w = __expf(s * inv_scale) - 1.0f;

    int h = lane >> 2;
    if ((lane & 3) == 0) atomicAdd(&g_denom[row * Hh + h], w);

    float* np = g_numer + (size_t)row * Dd + lane * 8;
    asm volatile("red.global.add.v4.f32 [%0], {%1, %2, %3, %4};"
                 :: "l"(np), "f"(w * v1.x), "f"(w * v1.y), "f"(w * v1.z), "f"(w * v1.w)
                 : "memory");
    asm volatile("red.global.add.v4.f32 [%0], {%1, %2, %3, %4};"
                 :: "l"(np + 4), "f"(w * v2.x), "f"(w * v2.y), "f"(w * v2.z), "f"(w * v2.w)
                 : "memory");
}

// ---------------------------------------------------------------------------
// Combine: attn[i, c] = (vsum[c] + numer[i, c]) / (N + denom[i, c/32])
// ---------------------------------------------------------------------------
__global__ void combine_kernel() {
    int i = blockIdx.x;
    int c = threadIdx.x;
    size_t idx = (size_t)i * Dd + c;
    float d = (float)Nn + g_denom[i * Hh + (c >> 5)];
    g_attn[idx] = (g_vsum[c] + g_numer[idx]) / d;
}

// ---------------------------------------------------------------------------
extern "C" void kernel_launch(void* const* d_in, const int* in_sizes, int n_in,
                              void* d_out, int out_size) {
    const float* x  = (const float*)d_in[0];
    const int*   ei = (const int*)d_in[1];     // int32 (JAX x64 disabled)
    const float* Wq = (const float*)d_in[2];
    const float* Wk = (const float*)d_in[3];
    const float* Wv = (const float*)d_in[4];
    const float* Wo = (const float*)d_in[5];
    const float* bo = (const float*)d_in[6];
    float*       out = (float*)d_out;

    zero_kernel<<<1024, 256>>>();
    gemm_qkv_kernel<<<dim3(Dd / 128, Nn / 64, 3), 128>>>(x, Wq, Wk, Wv);
    vsum_kernel<<<Nn / 64, 256>>>();
    edge_kernel<<<Ee / 8, 256>>>(ei);
    combine_kernel<<<Nn, Dd>>>();
    gemm_out_kernel<<<dim3(Dd / 128, Nn / 64, 1), 128>>>(Wo, bo, out);
}

// round 4
// speedup vs baseline: 1.6194x; 1.2821x over previous
#include <cuda_runtime.h>

// Problem constants
constexpr int Nn = 4096;   // nodes
constexpr int Dd = 256;    // model dim
constexpr int Hh = 8;      // heads
constexpr int Ee = 65536;  // edges

constexpr int BK   = 16;   // GEMM k-tile
constexpr int KPAD = 20;   // padded smem row (floats): banks (20r+c)&31 all distinct

// ---------------------------------------------------------------------------
// Scratch
// ---------------------------------------------------------------------------
__device__ float    g_Q[Nn * Dd];
__device__ float    g_K[Nn * Dd];
__device__ float    g_V[Nn * Dd];
__device__ float    g_numer[Nn * Dd];
__device__ float    g_attn[Nn * Dd];
__device__ float    g_denom[Nn * Hh];
__device__ float    g_vsum[Dd];
__device__ unsigned g_bitmap[(size_t)Nn * Nn / 32];
// tf32-rounded operands
__device__ float    g_xr[Nn * Dd];
__device__ float    g_Wqr[Dd * Dd];
__device__ float    g_Wkr[Dd * Dd];
__device__ float    g_Wvr[Dd * Dd];
__device__ float    g_Wor[Dd * Dd];

// ---------------------------------------------------------------------------
__device__ __forceinline__ float tf32_rna(float f) {
    unsigned u;
    asm("cvt.rna.tf32.f32 %0, %1;" : "=r"(u) : "f"(f));
    return __uint_as_float(u);
}

__global__ void zero_kernel() {
    int idx = blockIdx.x * blockDim.x + threadIdx.x;
    int stride = gridDim.x * blockDim.x;
    float4 fz = make_float4(0.f, 0.f, 0.f, 0.f);
    uint4  uz = make_uint4(0u, 0u, 0u, 0u);
    float4* n4 = (float4*)g_numer;
    uint4*  b4 = (uint4*)g_bitmap;
    for (int i = idx; i < Nn * Dd / 4; i += stride) n4[i] = fz;
    for (int i = idx; i < Nn * Nn / 32 / 4; i += stride) b4[i] = uz;
    for (int i = idx; i < Nn * Hh; i += stride) g_denom[i] = 0.0f;
    for (int i = idx; i < Dd; i += stride) g_vsum[i] = 0.0f;
}

// Round-to-nearest tf32 pre-pass for all GEMM operands (removes HMMA
// truncation bias; errors become unbiased -> sqrt-N cancellation in dots).
__global__ void round_kernel(const float* __restrict__ x,
                             const float* __restrict__ Wq,
                             const float* __restrict__ Wk,
                             const float* __restrict__ Wv,
                             const float* __restrict__ Wo) {
    int idx = blockIdx.x * blockDim.x + threadIdx.x;
    int stride = gridDim.x * blockDim.x;
    for (int i = idx; i < Nn * Dd; i += stride) g_xr[i] = tf32_rna(x[i]);
    for (int i = idx; i < Dd * Dd; i += stride) {
        g_Wqr[i] = tf32_rna(Wq[i]);
        g_Wkr[i] = tf32_rna(Wk[i]);
        g_Wvr[i] = tf32_rna(Wv[i]);
        g_Wor[i] = tf32_rna(Wo[i]);
    }
}

// ---------------------------------------------------------------------------
// TF32 tensor-core GEMM: C[M,256] = A[M,256] @ W[256,256]^T (+ optional bias)
// BM=128, BN=128, BK=16; 256 threads = 8 warps (2m x 4n), warp tile 64x32.
// cp.async double-buffered staging; smem rows padded to 20 floats.
// ---------------------------------------------------------------------------
__device__ __forceinline__ unsigned smem_u32(const void* p) {
    return (unsigned)__cvta_generic_to_shared(p);
}
__device__ __forceinline__ void cp_async16(unsigned dst, const void* src) {
    asm volatile("cp.async.cg.shared.global [%0], [%1], 16;" :: "r"(dst), "l"(src));
}
__device__ __forceinline__ void cp_commit() {
    asm volatile("cp.async.commit_group;" ::: "memory");
}
template <int N> __device__ __forceinline__ void cp_wait() {
    asm volatile("cp.async.wait_group %0;" :: "n"(N) : "memory");
}

__device__ __forceinline__ void mma_tf32(float* d, float a0, float a1, float a2, float a3,
                                         float b0, float b1) {
    asm volatile(
        "mma.sync.aligned.m16n8k8.row.col.f32.tf32.tf32.f32 "
        "{%0,%1,%2,%3}, {%4,%5,%6,%7}, {%8,%9}, {%0,%1,%2,%3};\n"
        : "+f"(d[0]), "+f"(d[1]), "+f"(d[2]), "+f"(d[3])
        : "r"(__float_as_uint(a0)), "r"(__float_as_uint(a1)),
          "r"(__float_as_uint(a2)), "r"(__float_as_uint(a3)),
          "r"(__float_as_uint(b0)), "r"(__float_as_uint(b1)));
}

__device__ __forceinline__ void gemm_body(const float* __restrict__ A,
                                          const float* __restrict__ W,
                                          const float* __restrict__ bias,
                                          float* __restrict__ C) {
    __shared__ __align__(16) float As[2][128 * KPAD];
    __shared__ __align__(16) float Ws[2][128 * KPAD];

    const int tid  = threadIdx.x;
    const int lane = tid & 31;
    const int wid  = tid >> 5;
    const int wm0  = (wid & 1) * 64;   // warp m-offset in tile
    const int wn0  = (wid >> 1) * 32;  // warp n-offset in tile
    const int m0   = blockIdx.y * 128;
    const int n0   = blockIdx.x * 128;

    const int r = lane >> 2;   // 0..7
    const int c = lane & 3;    // 0..3

    // Staging assignment: 4 cp.async x 16B per thread per tile
    const int ldrow = tid >> 2;        // 0..63
    const int ldk   = (tid & 3) * 4;   // 0,4,8,12

    float d[4][4][4];
#pragma unroll
    for (int i = 0; i < 4; i++)
#pragma unroll
        for (int j = 0; j < 4; j++)
#pragma unroll
            for (int q = 0; q < 4; q++) d[i][j][q] = 0.0f;

    // ---- stage tile t into buffer s ----
    auto do_stage = [&](int s, int t) {
        unsigned a_dst = smem_u32(&As[s][ldrow * KPAD + ldk]);
        cp_async16(a_dst, &A[(size_t)(m0 + ldrow) * Dd + t * BK + ldk]);
        cp_async16(a_dst + 64 * KPAD * 4, &A[(size_t)(m0 + ldrow + 64) * Dd + t * BK + ldk]);
        unsigned w_dst = smem_u32(&Ws[s][ldrow * KPAD + ldk]);
        cp_async16(w_dst, &W[(size_t)(n0 + ldrow) * Dd + t * BK + ldk]);
        cp_async16(w_dst + 64 * KPAD * 4, &W[(size_t)(n0 + ldrow + 64) * Dd + t * BK + ldk]);
        cp_commit();
    };

    do_stage(0, 0);

    constexpr int NT = Dd / BK;  // 16 tiles
    for (int t = 0; t < NT; t++) {
        if (t + 1 < NT) { do_stage((t + 1) & 1, t + 1); cp_wait<1>(); }
        else            { cp_wait<0>(); }
        __syncthreads();
        const int s = t & 1;

#pragma unroll
        for (int kk = 0; kk < BK; kk += 8) {
            float a[4][4], b[4][2];
#pragma unroll
            for (int i = 0; i < 4; i++) {
                const float* p = &As[s][(wm0 + 16 * i + r) * KPAD + kk + c];
                a[i][0] = p[0];
                a[i][1] = p[8 * KPAD];
                a[i][2] = p[4];
                a[i][3] = p[8 * KPAD + 4];
            }
#pragma unroll
            for (int j = 0; j < 4; j++) {
                const float* p = &Ws[s][(wn0 + 8 * j + r) * KPAD + kk + c];
                b[j][0] = p[0];
                b[j][1] = p[4];
            }
#pragma unroll
            for (int i = 0; i < 4; i++)
#pragma unroll
                for (int j = 0; j < 4; j++)
                    mma_tf32(d[i][j], a[i][0], a[i][1], a[i][2], a[i][3],
                             b[j][0], b[j][1]);
        }
        __syncthreads();
    }

    // Epilogue: c0/c1 at (r, 2c), (r, 2c+1); c2/c3 at (r+8, ...)
#pragma unroll
    for (int i = 0; i < 4; i++) {
#pragma unroll
        for (int j = 0; j < 4; j++) {
            int m = m0 + wm0 + 16 * i + r;
            int n = n0 + wn0 + 8 * j + 2 * c;
            float2 v0 = make_float2(d[i][j][0], d[i][j][1]);
            float2 v1 = make_float2(d[i][j][2], d[i][j][3]);
            if (bias) {
                float bx = bias[n], by = bias[n + 1];
                v0.x += bx; v0.y += by;
                v1.x += bx; v1.y += by;
            }
            *(float2*)&C[(size_t)m * Dd + n] = v0;
            *(float2*)&C[(size_t)(m + 8) * Dd + n] = v1;
        }
    }
}

__global__ __launch_bounds__(256) void gemm_qkv_kernel() {
    const float* W = (blockIdx.z == 0) ? g_Wqr : (blockIdx.z == 1) ? g_Wkr : g_Wvr;
    float* C = (blockIdx.z == 0) ? g_Q : (blockIdx.z == 1) ? g_K : g_V;
    gemm_body(g_xr, W, nullptr, C);
}

__global__ __launch_bounds__(256) void gemm_out_kernel(const float* __restrict__ bo,
                                                       float* __restrict__ out) {
    gemm_body(g_attn, g_Wor, bo, out);
}

// ---------------------------------------------------------------------------
__global__ void vsum_kernel() {
    int c = threadIdx.x;
    int r0 = blockIdx.x * 64;
    float s = 0.0f;
#pragma unroll 8
    for (int r = 0; r < 64; r++) s += g_V[(size_t)(r0 + r) * Dd + c];
    atomicAdd(&g_vsum[c], s);
}

// ---------------------------------------------------------------------------
// Edge kernel: one warp per edge. Lane l covers dims [l*8, l*8+8).
// ---------------------------------------------------------------------------
__global__ __launch_bounds__(256) void edge_kernel(const int* __restrict__ ei) {
    int warp = (blockIdx.x * blockDim.x + threadIdx.x) >> 5;
    int lane = threadIdx.x & 31;
    if (warp >= Ee) return;

    int row = ei[warp] & (Nn - 1);
    int col = ei[Ee + warp] & (Nn - 1);

    unsigned key = (unsigned)row * (unsigned)Nn + (unsigned)col;
    int skip = 0;
    if (lane == 0) {
        unsigned old = atomicOr(&g_bitmap[key >> 5], 1u << (key & 31));
        skip = (old >> (key & 31)) & 1;
    }
    skip = __shfl_sync(0xffffffffu, skip, 0);
    if (skip) return;

    const float* q = g_Q + (size_t)row * Dd + lane * 8;
    const float* k = g_K + (size_t)col * Dd + lane * 8;
    const float* v = g_V + (size_t)col * Dd + lane * 8;
    float4 q1 = *(const float4*)q;
    float4 q2 = *(const float4*)(q + 4);
    float4 k1 = *(const float4*)k;
    float4 k2 = *(const float4*)(k + 4);
    float4 v1 = *(const float4*)v;
    float4 v2 = *(const float4*)(v + 4);

    float s = q1.x * k1.x + q1.y * k1.y + q1.z * k1.z + q1.w * k1.w
            + q2.x * k2.x + q2.y * k2.y + q2.z * k2.z + q2.w * k2.w;
    s += __shfl_xor_sync(0xffffffffu, s, 1);
    s += __shfl_xor_sync(0xffffffffu, s, 2);

    const float inv_scale = 0.17677669529663687f;  // 1/sqrt(32)
    float w = __expf(s * inv_scale) - 1.0f;

    int h = lane >> 2;
    if ((lane & 3) == 0) atomicAdd(&g_denom[row * Hh + h], w);

    float* np = g_numer + (size_t)row * Dd + lane * 8;
    asm volatile("red.global.add.v4.f32 [%0], {%1, %2, %3, %4};"
                 :: "l"(np), "f"(w * v1.x), "f"(w * v1.y), "f"(w * v1.z), "f"(w * v1.w)
                 : "memory");
    asm volatile("red.global.add.v4.f32 [%0], {%1, %2, %3, %4};"
                 :: "l"(np + 4), "f"(w * v2.x), "f"(w * v2.y), "f"(w * v2.z), "f"(w * v2.w)
                 : "memory");
}

// ---------------------------------------------------------------------------
// Combine: attn[i, c] = (vsum[c] + numer[i, c]) / (N + denom[i, c/32]),
// rounded to tf32 (it feeds the tf32 out-projection GEMM).
// ---------------------------------------------------------------------------
__global__ void combine_kernel() {
    int i = blockIdx.x;
    int c = threadIdx.x;
    size_t idx = (size_t)i * Dd + c;
    float d = (float)Nn + g_denom[i * Hh + (c >> 5)];
    g_attn[idx] = tf32_rna((g_vsum[c] + g_numer[idx]) / d);
}

// ---------------------------------------------------------------------------
extern "C" void kernel_launch(void* const* d_in, const int* in_sizes, int n_in,
                              void* d_out, int out_size) {
    const float* x  = (const float*)d_in[0];
    const int*   ei = (const int*)d_in[1];     // int32 (JAX x64 disabled)
    const float* Wq = (const float*)d_in[2];
    const float* Wk = (const float*)d_in[3];
    const float* Wv = (const float*)d_in[4];
    const float* Wo = (const float*)d_in[5];
    const float* bo = (const float*)d_in[6];
    float*       out = (float*)d_out;

    zero_kernel<<<1024, 256>>>();
    round_kernel<<<512, 256>>>(x, Wq, Wk, Wv, Wo);
    gemm_qkv_kernel<<<dim3(Dd / 128, Nn / 128, 3), 256>>>();
    vsum_kernel<<<Nn / 64, 256>>>();
    edge_kernel<<<Ee / 8, 256>>>(ei);
    combine_kernel<<<Nn, Dd>>>();
    gemm_out_kernel<<<dim3(Dd / 128, Nn / 128, 1), 256>>>(bo, out);
}